// round 15
// baseline (speedup 1.0000x reference)
#include <cuda_runtime.h>
#include <cuda_bf16.h>
#include <math.h>
#include <stdint.h>

// Problem constants
constexpr int Bv = 128, Nv = 512, Kv = 10, Fv = 128, TFv = 256, Cv = 40;
constexpr int S2N = 11;     // cone nodes per b: {0} U neigh[b,0]
constexpr int THREADS = 512;

// Fused kernel dynamic smem (bytes)
constexpr int WPITCH  = 264;                 // bf16/row (528 B, LDSM conflict-free)
constexpr int W_PLANE = 128 * WPITCH * 2;    // 67584 (one split part of W0)
constexpr int A_OFF   = 2 * W_PLANE;         // 135168
constexpr int A_PLANE = 16 * WPITCH * 2;     // 8448  (16 padded rows)
constexpr int H1_OFF  = A_OFF + 2 * A_PLANE; // 152064
constexpr int SMEM_BYTES = H1_OFF + S2N * 128 * 4;  // 157696

// Globals (allocation-free rule)
__device__ __align__(16) __nv_bfloat16 g_w0b[2 * 128 * WPITCH];  // pre-split W0
__device__ __align__(16) float g_M[64 * 256];   // M = l1w @ W1
__device__ float g_c[64];                       // c = l1w @ b1 + l1b
__device__ float g_sum[64];
__device__ float g_sumsq[64];
__device__ unsigned int g_bar1 = 0;
__device__ unsigned int g_bar2 = 0;

// ---------------- HMMA / LDSM helpers ----------------
__device__ __forceinline__ void mma_bf16(float* c, const uint32_t* a,
                                         uint32_t b0, uint32_t b1) {
    asm volatile(
        "mma.sync.aligned.m16n8k16.row.col.f32.bf16.bf16.f32 "
        "{%0,%1,%2,%3}, {%4,%5,%6,%7}, {%8,%9}, {%0,%1,%2,%3};"
        : "+f"(c[0]), "+f"(c[1]), "+f"(c[2]), "+f"(c[3])
        : "r"(a[0]), "r"(a[1]), "r"(a[2]), "r"(a[3]), "r"(b0), "r"(b1));
}
__device__ __forceinline__ void ldsm_x4(uint32_t* r, uint32_t addr) {
    asm volatile("ldmatrix.sync.aligned.m8n8.x4.shared.b16 {%0,%1,%2,%3}, [%4];"
                 : "=r"(r[0]), "=r"(r[1]), "=r"(r[2]), "=r"(r[3]) : "r"(addr));
}
__device__ __forceinline__ uint32_t smem_u32(const void* p) {
    uint32_t a;
    asm("{ .reg .u64 t; cvta.to.shared.u64 t, %1; cvt.u32.u64 %0, t; }"
        : "=r"(a) : "l"(p));
    return a;
}
__device__ __forceinline__ void split4(const float4 v, uint2& hi, uint2& lo) {
    __nv_bfloat16 h[4], l[4];
    const float va[4] = {v.x, v.y, v.z, v.w};
    #pragma unroll
    for (int q = 0; q < 4; ++q) {
        h[q] = __float2bfloat16(va[q]);
        l[q] = __float2bfloat16(va[q] - __bfloat162float(h[q]));
    }
    hi = *(uint2*)h;
    lo = *(uint2*)l;
}

// ---------------- prep: M = l1w@W1, c = l1w@b1 + l1b, W0 bf16 split ----------------
__global__ __launch_bounds__(256) void prep_kernel(
    const float* __restrict__ w_sage, const float* __restrict__ b_sage,
    const float* __restrict__ l1w, const float* __restrict__ l1b)
{
    const int blk = blockIdx.x, t = threadIdx.x;
    if (blk < 64) {
        // M[j][k], j = blk, k = t
        const int j = blk;
        const float* wr = l1w + j * 128;
        const float* w1 = w_sage + 32768;     // layer-1 weights [128][256]
        float s0 = 0.f, s1 = 0.f;
        #pragma unroll 8
        for (int f = 0; f < 128; f += 2) {
            s0 = fmaf(__ldg(wr + f),     __ldg(w1 + f * 256 + t),       s0);
            s1 = fmaf(__ldg(wr + f + 1), __ldg(w1 + (f + 1) * 256 + t), s1);
        }
        g_M[j * 256 + t] = s0 + s1;
        // c[j]: thread-parallel products, serial reduce by t==0
        __shared__ float red[128];
        if (t < 128) red[t] = __ldg(wr + t) * __ldg(b_sage + 128 + t);
        __syncthreads();
        if (t == 0) {
            float c = __ldg(l1b + j);
            #pragma unroll 4
            for (int f = 0; f < 128; ++f) c += red[f];
            g_c[j] = c;
        }
    } else {
        // W0 split: linear value v = (blk-64)*256 + t  (v < 32768)
        const int v = (blk - 64) * 256 + t;
        const int n = v >> 8, k = v & 255;
        const float val = __ldg(w_sage + v);
        const __nv_bfloat16 hi = __float2bfloat16(val);
        g_w0b[n * WPITCH + k] = hi;
        g_w0b[128 * WPITCH + n * WPITCH + k] =
            __float2bfloat16(val - __bfloat162float(hi));
    }
}

// ---------------- single fused kernel: one CTA per batch element ----------------
__global__ __launch_bounds__(THREADS, 1) void fused_all_kernel(
    const float* __restrict__ x, const int* __restrict__ neigh,
    const float* __restrict__ b_sage,
    const float* __restrict__ gamma, const float* __restrict__ beta,
    const float* __restrict__ l2w, const float* __restrict__ l2b,
    float* __restrict__ out)
{
    extern __shared__ char sm[];
    __shared__ float a2[256];
    __shared__ float redl[8][64];          // combined GEMV partials
    __shared__ float s_w[64][40];          // l2w transposed (staged pre-barrier)
    __shared__ float s_b2[Cv];
    __shared__ float s_r[64];              // this CTA's z row -> relu'd row
    const uint32_t smb = smem_u32(sm);
    const int t = threadIdx.x, lane = t & 31, warp = t >> 5;
    const int b = blockIdx.x;

    // ---- stage W0 planes: pure uint4 copy of pre-split bf16 (135168 B) ----
    {
        const uint4* src = (const uint4*)g_w0b;   // 8448 uint4
        uint4* dst = (uint4*)sm;
        for (int o = t; o < 8448; o += THREADS)
            dst[o] = __ldg(src + o);
    }

    // ---- stage l2w transposed + l2b (used after barrier) ----
    for (int o = t; o < Cv * 64; o += THREADS) {
        const int c = o >> 6, j = o & 63;
        s_w[j][c] = __ldg(l2w + o);
    }
    if (t < Cv) s_b2[t] = __ldg(l2b + t);

    // ---- zero padded A rows 11..15 (both planes) ----
    if (t < 330) {
        const uint4 zz = make_uint4(0, 0, 0, 0);
        const int p = t / 165, i = t - p * 165;
        *(uint4*)(sm + A_OFF + p * A_PLANE + 11 * 528 + i * 16) = zz;
    }

    // ---- gather-mean + self into A planes: one row per warp, single round ----
    if (warp < S2N) {
        const int r = warp;
        const int m = (r == 0) ? 0 : __ldg(neigh + (b * Nv) * Kv + (r - 1));
        const int* nb = neigh + (b * Nv + m) * Kv;
        float4 a4 = make_float4(0.f, 0.f, 0.f, 0.f);
        #pragma unroll
        for (int k = 0; k < Kv; ++k) {
            const int idx = __ldg(nb + k);
            const float4 v = __ldg((const float4*)(x + (b * Nv + idx) * Fv) + lane);
            a4.x += v.x; a4.y += v.y; a4.z += v.z; a4.w += v.w;
        }
        const float inv = 1.0f / Kv;
        a4 = make_float4(a4.x * inv, a4.y * inv, a4.z * inv, a4.w * inv);
        uint2 hi, lo;
        split4(a4, hi, lo);
        char* p0 = sm + A_OFF + r * 528 + lane * 8;
        *(uint2*)p0 = hi;
        *(uint2*)(p0 + A_PLANE) = lo;
        const float4 hv = __ldg((const float4*)(x + (b * Nv + m) * Fv) + lane);
        split4(hv, hi, lo);
        *(uint2*)(p0 + 256) = hi;
        *(uint2*)(p0 + 256 + A_PLANE) = lo;
    }
    __syncthreads();

    // ---- MMA: warps 0-7 only; 16m x 128n, K=256; each warp owns 16 cols ----
    const int qr = lane >> 2, qc = (lane & 3) * 2;
    if (warp < 8) {
        const int wn = warp * 16;
        uint32_t aaddr[2], baddr[2];
        {
            const int ra = (lane & 7) + ((lane >> 3) & 1) * 8;
            const int ca = ((lane >> 4) & 1) * 16;
            #pragma unroll
            for (int p = 0; p < 2; ++p)
                aaddr[p] = smb + A_OFF + p * A_PLANE + ra * 528 + ca;
            const int rb = (lane & 7) + ((lane >> 4) & 1) * 8;
            const int cb = ((lane >> 3) & 1) * 16;
            #pragma unroll
            for (int p = 0; p < 2; ++p)
                baddr[p] = smb + p * W_PLANE + (wn + rb) * 528 + cb;
        }

        float acc[2][4];
        #pragma unroll
        for (int nf = 0; nf < 2; ++nf)
            #pragma unroll
            for (int q = 0; q < 4; ++q) acc[nf][q] = 0.f;

        #pragma unroll
        for (int ks = 0; ks < 16; ++ks) {
            const uint32_t off = ks * 32;
            uint32_t AH[4], AL[4], BH[4], BL[4];
            ldsm_x4(AH, aaddr[0] + off);
            ldsm_x4(AL, aaddr[1] + off);
            ldsm_x4(BH, baddr[0] + off);
            ldsm_x4(BL, baddr[1] + off);
            #pragma unroll
            for (int nf = 0; nf < 2; ++nf) {
                const uint32_t bh0 = BH[nf * 2], bh1 = BH[nf * 2 + 1];
                const uint32_t bl0 = BL[nf * 2], bl1 = BL[nf * 2 + 1];
                mma_bf16(acc[nf], AH, bh0, bh1);
                mma_bf16(acc[nf], AL, bh0, bh1);
                mma_bf16(acc[nf], AH, bl0, bl1);
            }
        }

        // epilogue: + bias, write h1 cone (rows 0..10) to smem
        float* h1s = (float*)(sm + H1_OFF);   // [11][128]
        #pragma unroll
        for (int nf = 0; nf < 2; ++nf) {
            const int col = wn + nf * 8 + qc;
            const float b0 = __ldg(b_sage + col);
            const float b1 = __ldg(b_sage + col + 1);
            h1s[qr * 128 + col]     = acc[nf][0] + b0;
            h1s[qr * 128 + col + 1] = acc[nf][1] + b1;
            if (qr < 3) {
                h1s[(qr + 8) * 128 + col]     = acc[nf][2] + b0;
                h1s[(qr + 8) * 128 + col + 1] = acc[nf][3] + b1;
            }
        }
    }
    __syncthreads();

    // ---- a2 = [mean_{s=1..10} h1s[s], h1s[0]] ----
    {
        float* h1s = (float*)(sm + H1_OFF);
        if (t < 128) {
            float a = 0.f;
            #pragma unroll
            for (int s = 1; s < 11; ++s) a += h1s[s * 128 + t];
            a2[t] = a * (1.0f / Kv);
            a2[128 + t] = h1s[t];
        }
    }
    __syncthreads();

    // ---- z[b,j] = a2 . M[j,:] + c[j]  (combined layer2+lin1, 8-way split) ----
    {
        const int j = t & 63, seg = t >> 6;      // 8 segments of 32 k each
        const float4* mr = (const float4*)(g_M + j * 256 + seg * 32);
        const float4* ar = (const float4*)(a2 + seg * 32);
        float s0 = 0.f, s1 = 0.f;
        #pragma unroll
        for (int q = 0; q < 8; q += 2) {
            const float4 w0 = __ldg(mr + q),     a0 = ar[q];
            const float4 w1 = __ldg(mr + q + 1), a1 = ar[q + 1];
            s0 = fmaf(a0.x, w0.x, s0); s0 = fmaf(a0.y, w0.y, s0);
            s0 = fmaf(a0.z, w0.z, s0); s0 = fmaf(a0.w, w0.w, s0);
            s1 = fmaf(a1.x, w1.x, s1); s1 = fmaf(a1.y, w1.y, s1);
            s1 = fmaf(a1.z, w1.z, s1); s1 = fmaf(a1.w, w1.w, s1);
        }
        redl[seg][j] = s0 + s1;
    }
    __syncthreads();

    // ---- own z row -> smem + atomic global BN accumulators ----
    if (t < 64) {
        float zv = __ldg(&g_c[t]);
        #pragma unroll
        for (int g = 0; g < 8; ++g) zv += redl[g][t];
        s_r[t] = zv;
        atomicAdd(&g_sum[t], zv);
        atomicAdd(&g_sumsq[t], zv * zv);
    }

    // ================= device-wide barrier (R13 measured-best form) =================
    __threadfence();
    __syncthreads();
    if (t == 0) {
        atomicAdd(&g_bar1, 1u);
        while (atomicAdd(&g_bar1, 0u) < (unsigned)Bv) { }
    }
    __syncthreads();

    // ================= phase B: finish own row only =================
    if (t < 64) {
        const float s  = __ldcg(&g_sum[t]);
        const float q  = __ldcg(&g_sumsq[t]);
        const float mu  = s * (1.0f / Bv);
        const float var = q * (1.0f / Bv) - mu * mu;
        const float sc  = __ldg(gamma + t) * rsqrtf(var + 1e-5f);
        const float sh  = __ldg(beta + t) - mu * sc;
        s_r[t] = fmaxf(s_r[t] * sc + sh, 0.f);
    }
    __syncthreads();

    // warp 0: lin2 (2 cols per lane, even/odd-j dual accs) + softmax via shuffle
    if (warp == 0) {
        float lgA0 = s_b2[lane], lgA1 = 0.f;          // lane < 32 < Cv
        const bool hasB = (lane < Cv - 32);
        float lgB0 = hasB ? s_b2[lane + 32] : 0.f, lgB1 = 0.f;
        #pragma unroll 8
        for (int j = 0; j < 64; j += 2) {
            const float z0 = s_r[j], z1 = s_r[j + 1];
            lgA0 = fmaf(z0, s_w[j][lane], lgA0);
            lgA1 = fmaf(z1, s_w[j + 1][lane], lgA1);
            if (hasB) {
                lgB0 = fmaf(z0, s_w[j][lane + 32], lgB0);
                lgB1 = fmaf(z1, s_w[j + 1][lane + 32], lgB1);
            }
        }
        const float lgA = lgA0 + lgA1;
        const float lgB = lgB0 + lgB1;
        float m = lgA;
        if (hasB) m = fmaxf(m, lgB);
        #pragma unroll
        for (int o = 16; o > 0; o >>= 1)
            m = fmaxf(m, __shfl_xor_sync(0xFFFFFFFF, m, o));
        float eA = expf(lgA - m);
        float eB = hasB ? expf(lgB - m) : 0.f;
        float s = eA + eB;
        #pragma unroll
        for (int o = 16; o > 0; o >>= 1)
            s += __shfl_xor_sync(0xFFFFFFFF, s, o);
        const float r = 1.0f / s;
        out[b * Cv + lane] = eA * r;
        if (hasB) out[b * Cv + lane + 32] = eB * r;
    }

    // ---- reset counters/accumulators for next graph replay ----
    __syncthreads();   // all readers of g_sum/g_sumsq are done in this CTA
    if (t == 0) {
        if (atomicAdd(&g_bar2, 1u) == (unsigned)(Bv - 1)) {
            #pragma unroll
            for (int j = 0; j < 64; ++j) { g_sum[j] = 0.f; g_sumsq[j] = 0.f; }
            g_bar1 = 0u;
            g_bar2 = 0u;
            __threadfence();
        }
    }
}

extern "C" void kernel_launch(void* const* d_in, const int* in_sizes, int n_in,
                              void* d_out, int out_size) {
    const float* x      = (const float*)d_in[0];
    const int*   neigh  = (const int*)  d_in[1];
    const float* w_sage = (const float*)d_in[2];
    const float* b_sage = (const float*)d_in[3];
    const float* l1w    = (const float*)d_in[4];
    const float* l1b    = (const float*)d_in[5];
    const float* gamma  = (const float*)d_in[6];
    const float* beta   = (const float*)d_in[7];
    const float* l2w    = (const float*)d_in[8];
    const float* l2b    = (const float*)d_in[9];
    float* out = (float*)d_out;

    cudaFuncSetAttribute(fused_all_kernel,
                         cudaFuncAttributeMaxDynamicSharedMemorySize, SMEM_BYTES);

    prep_kernel<<<192, 256>>>(w_sage, b_sage, l1w, l1b);
    fused_all_kernel<<<Bv, THREADS, SMEM_BYTES>>>(x, neigh, b_sage,
                                                  gamma, beta, l2w, l2b, out);
}

// round 16
// speedup vs baseline: 1.1951x; 1.1951x over previous
#include <cuda_runtime.h>
#include <cuda_bf16.h>
#include <math.h>
#include <stdint.h>

// Problem constants
constexpr int Bv = 128, Nv = 512, Kv = 10, Fv = 128, TFv = 256, Cv = 40;
constexpr int S2N = 11;     // cone nodes per b: {0} U neigh[b,0]
constexpr int THREADS = 1024;

// Fused kernel dynamic smem (bytes)
constexpr int WPITCH  = 264;                 // bf16/row (528 B, LDSM conflict-free)
constexpr int W_PLANE = 128 * WPITCH * 2;    // 67584 (one split part of W0)
constexpr int A_OFF   = 2 * W_PLANE;         // 135168
constexpr int A_PLANE = 16 * WPITCH * 2;     // 8448  (16 padded rows)
constexpr int H1_OFF  = A_OFF + 2 * A_PLANE; // 152064
constexpr int SMEM_BYTES = H1_OFF + S2N * 128 * 4;  // 157696

// Globals (allocation-free rule)
__device__ float g_sum[64];
__device__ float g_sumsq[64];
__device__ unsigned int g_bar1 = 0;
__device__ unsigned int g_bar2 = 0;

// ---------------- HMMA / LDSM helpers ----------------
__device__ __forceinline__ void mma_bf16(float* c, const uint32_t* a,
                                         uint32_t b0, uint32_t b1) {
    asm volatile(
        "mma.sync.aligned.m16n8k16.row.col.f32.bf16.bf16.f32 "
        "{%0,%1,%2,%3}, {%4,%5,%6,%7}, {%8,%9}, {%0,%1,%2,%3};"
        : "+f"(c[0]), "+f"(c[1]), "+f"(c[2]), "+f"(c[3])
        : "r"(a[0]), "r"(a[1]), "r"(a[2]), "r"(a[3]), "r"(b0), "r"(b1));
}
__device__ __forceinline__ void ldsm_x4(uint32_t* r, uint32_t addr) {
    asm volatile("ldmatrix.sync.aligned.m8n8.x4.shared.b16 {%0,%1,%2,%3}, [%4];"
                 : "=r"(r[0]), "=r"(r[1]), "=r"(r[2]), "=r"(r[3]) : "r"(addr));
}
__device__ __forceinline__ uint32_t smem_u32(const void* p) {
    uint32_t a;
    asm("{ .reg .u64 t; cvta.to.shared.u64 t, %1; cvt.u32.u64 %0, t; }"
        : "=r"(a) : "l"(p));
    return a;
}
__device__ __forceinline__ void split4(const float4 v, uint2& hi, uint2& lo) {
    __nv_bfloat16 h[4], l[4];
    const float va[4] = {v.x, v.y, v.z, v.w};
    #pragma unroll
    for (int q = 0; q < 4; ++q) {
        h[q] = __float2bfloat16(va[q]);
        l[q] = __float2bfloat16(va[q] - __bfloat162float(h[q]));
    }
    hi = *(uint2*)h;
    lo = *(uint2*)l;
}

// ---------------- single fused kernel: one CTA per batch element ----------------
__global__ __launch_bounds__(THREADS, 1) void fused_all_kernel(
    const float* __restrict__ x, const int* __restrict__ neigh,
    const float* __restrict__ w_sage, const float* __restrict__ b_sage,
    const float* __restrict__ l1w, const float* __restrict__ l1b,
    const float* __restrict__ gamma, const float* __restrict__ beta,
    const float* __restrict__ l2w, const float* __restrict__ l2b,
    float* __restrict__ out)
{
    extern __shared__ char sm[];
    __shared__ float a2[256];
    __shared__ float h2s[128];
    __shared__ float redh[8][128];         // h2 GEMV partials
    __shared__ float redl[16][64];         // lin1 partials
    __shared__ float s_w[64][40];          // l2w transposed (staged pre-barrier)
    __shared__ float s_b2[Cv];
    __shared__ float s_r[64];              // this CTA's z row -> relu'd row
    const uint32_t smb = smem_u32(sm);
    const int t = threadIdx.x, lane = t & 31, warp = t >> 5;
    const int b = blockIdx.x;

    // ---- stage + split W0 (fp32 -> bf16 hi/lo planes), coalesced, 8 rounds ----
    {
        const float4* src = (const float4*)w_sage;   // layer 0: 8192 float4
        #pragma unroll
        for (int i = 0; i < 8; ++i) {
            const int idx4 = t + i * THREADS;
            const float4 v = __ldg(src + idx4);
            const int n  = idx4 >> 6;
            const int k4 = (idx4 & 63) * 4;
            uint2 hi, lo;
            split4(v, hi, lo);
            char* p = sm + n * 528 + k4 * 2;
            *(uint2*)p = hi;
            *(uint2*)(p + W_PLANE) = lo;
        }
    }

    // ---- stage l2w transposed + l2b (used after barrier) ----
    for (int o = t; o < Cv * 64; o += THREADS) {
        const int c = o >> 6, j = o & 63;
        s_w[j][c] = __ldg(l2w + o);
    }
    if (t < Cv) s_b2[t] = __ldg(l2b + t);

    // ---- zero padded A rows 11..15 (both planes) ----
    if (t < 330) {
        const uint4 zz = make_uint4(0, 0, 0, 0);
        const int p = t / 165, i = t - p * 165;
        *(uint4*)(sm + A_OFF + p * A_PLANE + 11 * 528 + i * 16) = zz;
    }

    // ---- gather-mean + self into A planes: one row per warp, single round ----
    if (warp < S2N) {
        const int r = warp;
        const int m = (r == 0) ? 0 : __ldg(neigh + (b * Nv) * Kv + (r - 1));
        const int* nb = neigh + (b * Nv + m) * Kv;
        float4 a4 = make_float4(0.f, 0.f, 0.f, 0.f);
        #pragma unroll
        for (int k = 0; k < Kv; ++k) {
            const int idx = __ldg(nb + k);
            const float4 v = __ldg((const float4*)(x + (b * Nv + idx) * Fv) + lane);
            a4.x += v.x; a4.y += v.y; a4.z += v.z; a4.w += v.w;
        }
        const float inv = 1.0f / Kv;
        a4 = make_float4(a4.x * inv, a4.y * inv, a4.z * inv, a4.w * inv);
        uint2 hi, lo;
        split4(a4, hi, lo);
        char* p0 = sm + A_OFF + r * 528 + lane * 8;
        *(uint2*)p0 = hi;
        *(uint2*)(p0 + A_PLANE) = lo;
        const float4 hv = __ldg((const float4*)(x + (b * Nv + m) * Fv) + lane);
        split4(hv, hi, lo);
        *(uint2*)(p0 + 256) = hi;
        *(uint2*)(p0 + 256 + A_PLANE) = lo;
    }
    __syncthreads();

    // ---- MMA: warps 0-7 only; 16m x 128n, K=256; each warp owns 16 cols ----
    const int qr = lane >> 2, qc = (lane & 3) * 2;
    if (warp < 8) {
        const int wn = warp * 16;
        uint32_t aaddr[2], baddr[2];
        {
            const int ra = (lane & 7) + ((lane >> 3) & 1) * 8;
            const int ca = ((lane >> 4) & 1) * 16;
            #pragma unroll
            for (int p = 0; p < 2; ++p)
                aaddr[p] = smb + A_OFF + p * A_PLANE + ra * 528 + ca;
            const int rb = (lane & 7) + ((lane >> 4) & 1) * 8;
            const int cb = ((lane >> 3) & 1) * 16;
            #pragma unroll
            for (int p = 0; p < 2; ++p)
                baddr[p] = smb + p * W_PLANE + (wn + rb) * 528 + cb;
        }

        float acc[2][4];
        #pragma unroll
        for (int nf = 0; nf < 2; ++nf)
            #pragma unroll
            for (int q = 0; q < 4; ++q) acc[nf][q] = 0.f;

        #pragma unroll
        for (int ks = 0; ks < 16; ++ks) {
            const uint32_t off = ks * 32;
            uint32_t AH[4], AL[4], BH[4], BL[4];
            ldsm_x4(AH, aaddr[0] + off);
            ldsm_x4(AL, aaddr[1] + off);
            ldsm_x4(BH, baddr[0] + off);
            ldsm_x4(BL, baddr[1] + off);
            #pragma unroll
            for (int nf = 0; nf < 2; ++nf) {
                const uint32_t bh0 = BH[nf * 2], bh1 = BH[nf * 2 + 1];
                const uint32_t bl0 = BL[nf * 2], bl1 = BL[nf * 2 + 1];
                mma_bf16(acc[nf], AH, bh0, bh1);
                mma_bf16(acc[nf], AL, bh0, bh1);
                mma_bf16(acc[nf], AH, bl0, bl1);
            }
        }

        // epilogue: + bias, write h1 cone (rows 0..10) to smem
        float* h1s = (float*)(sm + H1_OFF);   // [11][128]
        #pragma unroll
        for (int nf = 0; nf < 2; ++nf) {
            const int col = wn + nf * 8 + qc;
            const float b0 = __ldg(b_sage + col);
            const float b1 = __ldg(b_sage + col + 1);
            h1s[qr * 128 + col]     = acc[nf][0] + b0;
            h1s[qr * 128 + col + 1] = acc[nf][1] + b1;
            if (qr < 3) {
                h1s[(qr + 8) * 128 + col]     = acc[nf][2] + b0;
                h1s[(qr + 8) * 128 + col + 1] = acc[nf][3] + b1;
            }
        }
    }
    __syncthreads();

    // ---- a2 = [mean_{s=1..10} h1s[s], h1s[0]] ----
    {
        float* h1s = (float*)(sm + H1_OFF);
        if (t < 128) {
            float a = 0.f;
            #pragma unroll
            for (int s = 1; s < 11; ++s) a += h1s[s * 128 + t];
            a2[t] = a * (1.0f / Kv);
            a2[128 + t] = h1s[t];
        }
    }
    __syncthreads();

    // ---- h2[j] = a2 . W1[j,:] + b1[j]  (fp32 exact, 8-way split, 2 accs) ----
    {
        const int j = t & 127, seg = t >> 7;     // 8 segments of 32 k each
        const float4* wr = (const float4*)(w_sage + 32768 + j * 256 + seg * 32);
        const float4* ar = (const float4*)(a2 + seg * 32);
        float s0 = 0.f, s1 = 0.f;
        #pragma unroll
        for (int q = 0; q < 8; q += 2) {
            const float4 w0 = __ldg(wr + q),     a0 = ar[q];
            const float4 w1 = __ldg(wr + q + 1), a1 = ar[q + 1];
            s0 = fmaf(a0.x, w0.x, s0); s0 = fmaf(a0.y, w0.y, s0);
            s0 = fmaf(a0.z, w0.z, s0); s0 = fmaf(a0.w, w0.w, s0);
            s1 = fmaf(a1.x, w1.x, s1); s1 = fmaf(a1.y, w1.y, s1);
            s1 = fmaf(a1.z, w1.z, s1); s1 = fmaf(a1.w, w1.w, s1);
        }
        redh[seg][j] = s0 + s1;
    }
    __syncthreads();
    if (t < 128) {
        float h = __ldg(b_sage + 128 + t);
        #pragma unroll
        for (int g = 0; g < 8; ++g) h += redh[g][t];
        h2s[t] = h;
    }
    __syncthreads();

    // ---- z[b,j] = h2 . l1w[j,:] + l1b[j]  (16-way split) ----
    {
        const int j = t & 63, seg = t >> 6;      // 16 segments of 8 k each
        const float4* wr = (const float4*)(l1w + j * 128 + seg * 8);
        const float4* hr = (const float4*)(h2s + seg * 8);
        const float4 w0 = __ldg(wr + 0), a0 = hr[0];
        const float4 w1 = __ldg(wr + 1), a1 = hr[1];
        float s0 = 0.f, s1 = 0.f;
        s0 = fmaf(a0.x, w0.x, s0); s0 = fmaf(a0.y, w0.y, s0);
        s0 = fmaf(a0.z, w0.z, s0); s0 = fmaf(a0.w, w0.w, s0);
        s1 = fmaf(a1.x, w1.x, s1); s1 = fmaf(a1.y, w1.y, s1);
        s1 = fmaf(a1.z, w1.z, s1); s1 = fmaf(a1.w, w1.w, s1);
        redl[seg][j] = s0 + s1;
    }
    __syncthreads();

    // ---- own z row -> smem + atomic global BN accumulators ----
    if (t < 64) {
        float zv = __ldg(l1b + t);
        #pragma unroll
        for (int g = 0; g < 16; ++g) zv += redl[g][t];
        s_r[t] = zv;
        atomicAdd(&g_sum[t], zv);
        atomicAdd(&g_sumsq[t], zv * zv);
    }

    // ================= device-wide barrier (R13 measured-best form) =================
    // grid=128 <= 148 SMs at 1 CTA/SM: all CTAs co-resident, spin is safe.
    __threadfence();
    __syncthreads();
    if (t == 0) {
        atomicAdd(&g_bar1, 1u);
        while (atomicAdd(&g_bar1, 0u) < (unsigned)Bv) { }
    }
    __syncthreads();

    // ================= phase B: finish own row only =================
    if (t < 64) {
        const float s  = __ldcg(&g_sum[t]);       // .cg: bypass L1, read L2
        const float q  = __ldcg(&g_sumsq[t]);
        const float mu  = s * (1.0f / Bv);
        const float var = q * (1.0f / Bv) - mu * mu;
        const float sc  = __ldg(gamma + t) * rsqrtf(var + 1e-5f);
        const float sh  = __ldg(beta + t) - mu * sc;
        s_r[t] = fmaxf(s_r[t] * sc + sh, 0.f);
    }
    __syncthreads();

    // warp 0: lin2 (2 cols per lane, even/odd-j dual accs) + softmax via shuffle
    if (warp == 0) {
        float lgA0 = s_b2[lane], lgA1 = 0.f;          // lane < 32 < Cv
        const bool hasB = (lane < Cv - 32);
        float lgB0 = hasB ? s_b2[lane + 32] : 0.f, lgB1 = 0.f;
        #pragma unroll 8
        for (int j = 0; j < 64; j += 2) {
            const float z0 = s_r[j], z1 = s_r[j + 1];
            lgA0 = fmaf(z0, s_w[j][lane], lgA0);
            lgA1 = fmaf(z1, s_w[j + 1][lane], lgA1);
            if (hasB) {
                lgB0 = fmaf(z0, s_w[j][lane + 32], lgB0);
                lgB1 = fmaf(z1, s_w[j + 1][lane + 32], lgB1);
            }
        }
        const float lgA = lgA0 + lgA1;
        const float lgB = lgB0 + lgB1;
        float m = lgA;
        if (hasB) m = fmaxf(m, lgB);
        #pragma unroll
        for (int o = 16; o > 0; o >>= 1)
            m = fmaxf(m, __shfl_xor_sync(0xFFFFFFFF, m, o));
        float eA = expf(lgA - m);
        float eB = hasB ? expf(lgB - m) : 0.f;
        float s = eA + eB;
        #pragma unroll
        for (int o = 16; o > 0; o >>= 1)
            s += __shfl_xor_sync(0xFFFFFFFF, s, o);
        const float r = 1.0f / s;
        out[b * Cv + lane] = eA * r;
        if (hasB) out[b * Cv + lane + 32] = eB * r;
    }

    // ---- reset counters/accumulators for next graph replay ----
    __syncthreads();   // all readers of g_sum/g_sumsq are done in this CTA
    if (t == 0) {
        if (atomicAdd(&g_bar2, 1u) == (unsigned)(Bv - 1)) {
            #pragma unroll
            for (int j = 0; j < 64; ++j) { g_sum[j] = 0.f; g_sumsq[j] = 0.f; }
            g_bar1 = 0u;
            g_bar2 = 0u;
            __threadfence();
        }
    }
}

extern "C" void kernel_launch(void* const* d_in, const int* in_sizes, int n_in,
                              void* d_out, int out_size) {
    const float* x      = (const float*)d_in[0];
    const int*   neigh  = (const int*)  d_in[1];
    const float* w_sage = (const float*)d_in[2];
    const float* b_sage = (const float*)d_in[3];
    const float* l1w    = (const float*)d_in[4];
    const float* l1b    = (const float*)d_in[5];
    const float* gamma  = (const float*)d_in[6];
    const float* beta   = (const float*)d_in[7];
    const float* l2w    = (const float*)d_in[8];
    const float* l2b    = (const float*)d_in[9];
    float* out = (float*)d_out;

    cudaFuncSetAttribute(fused_all_kernel,
                         cudaFuncAttributeMaxDynamicSharedMemorySize, SMEM_BYTES);

    fused_all_kernel<<<Bv, THREADS, SMEM_BYTES>>>(x, neigh, w_sage, b_sage,
                                                  l1w, l1b, gamma, beta, l2w, l2b,
                                                  out);
}

// round 17
// speedup vs baseline: 1.3243x; 1.1081x over previous
#include <cuda_runtime.h>
#include <cuda_bf16.h>
#include <math.h>
#include <stdint.h>

// Problem constants
constexpr int Bv = 128, Nv = 512, Kv = 10, Fv = 128, TFv = 256, Cv = 40;
constexpr int S2N = 11;     // cone nodes per b: {0} U neigh[b,0]
constexpr int THREADS = 512;

// Fused kernel dynamic smem (bytes)
constexpr int WPITCH  = 264;                 // bf16/row (528 B, LDSM conflict-free)
constexpr int W_PLANE = 128 * WPITCH * 2;    // 67584 (one split part of W0)
constexpr int A_OFF   = 2 * W_PLANE;         // 135168
constexpr int A_PLANE = 16 * WPITCH * 2;     // 8448  (16 padded rows)
constexpr int H1_OFF  = A_OFF + 2 * A_PLANE; // 152064
constexpr int SMEM_BYTES = H1_OFF + S2N * 128 * 4;  // 157696

// Globals (allocation-free rule). Epoch-based barrier: no per-replay reset tail.
__device__ float g_sum[2][64];     // double-buffered by epoch parity
__device__ float g_sumsq[2][64];
__device__ unsigned int g_bar1  = 0;   // monotonic arrival counter
__device__ unsigned int g_epoch = 0;   // completed-launch count

// ---------------- HMMA / LDSM helpers ----------------
__device__ __forceinline__ void mma_bf16(float* c, const uint32_t* a,
                                         uint32_t b0, uint32_t b1) {
    asm volatile(
        "mma.sync.aligned.m16n8k16.row.col.f32.bf16.bf16.f32 "
        "{%0,%1,%2,%3}, {%4,%5,%6,%7}, {%8,%9}, {%0,%1,%2,%3};"
        : "+f"(c[0]), "+f"(c[1]), "+f"(c[2]), "+f"(c[3])
        : "r"(a[0]), "r"(a[1]), "r"(a[2]), "r"(a[3]), "r"(b0), "r"(b1));
}
__device__ __forceinline__ void ldsm_x4(uint32_t* r, uint32_t addr) {
    asm volatile("ldmatrix.sync.aligned.m8n8.x4.shared.b16 {%0,%1,%2,%3}, [%4];"
                 : "=r"(r[0]), "=r"(r[1]), "=r"(r[2]), "=r"(r[3]) : "r"(addr));
}
__device__ __forceinline__ uint32_t smem_u32(const void* p) {
    uint32_t a;
    asm("{ .reg .u64 t; cvta.to.shared.u64 t, %1; cvt.u32.u64 %0, t; }"
        : "=r"(a) : "l"(p));
    return a;
}
__device__ __forceinline__ void split4(const float4 v, uint2& hi, uint2& lo) {
    __nv_bfloat16 h[4], l[4];
    const float va[4] = {v.x, v.y, v.z, v.w};
    #pragma unroll
    for (int q = 0; q < 4; ++q) {
        h[q] = __float2bfloat16(va[q]);
        l[q] = __float2bfloat16(va[q] - __bfloat162float(h[q]));
    }
    hi = *(uint2*)h;
    lo = *(uint2*)l;
}

// ---------------- single fused kernel: one CTA per batch element ----------------
__global__ __launch_bounds__(THREADS, 1) void fused_all_kernel(
    const float* __restrict__ x, const int* __restrict__ neigh,
    const float* __restrict__ w_sage, const float* __restrict__ b_sage,
    const float* __restrict__ l1w, const float* __restrict__ l1b,
    const float* __restrict__ gamma, const float* __restrict__ beta,
    const float* __restrict__ l2w, const float* __restrict__ l2b,
    float* __restrict__ out)
{
    extern __shared__ char sm[];
    __shared__ float a2[256];
    __shared__ float h2s[128];
    __shared__ float redh[4][128];         // h2 GEMV partials
    __shared__ float redl[8][64];          // lin1 partials
    __shared__ float s_w[64][40];          // l2w transposed (staged pre-barrier)
    __shared__ float s_b2[Cv];
    __shared__ float s_r[64];              // this CTA's z row -> relu'd row
    const uint32_t smb = smem_u32(sm);
    const int t = threadIdx.x, lane = t & 31, warp = t >> 5;
    const int b = blockIdx.x;

    // Epoch read (constant during this launch; written only after all arrivals
    // of the PREVIOUS launch — launches serialize, so this is stable).
    const unsigned ep = *(volatile unsigned int*)&g_epoch;
    const int bank = ep & 1;

    // ---- stage + split W0 (fp32 -> bf16 hi/lo planes), coalesced, 16 rounds ----
    {
        const float4* src = (const float4*)w_sage;   // layer 0: 8192 float4
        #pragma unroll
        for (int i = 0; i < 16; ++i) {
            const int idx4 = t + i * THREADS;
            const float4 v = __ldg(src + idx4);
            const int n  = idx4 >> 6;
            const int k4 = (idx4 & 63) * 4;
            uint2 hi, lo;
            split4(v, hi, lo);
            char* p = sm + n * 528 + k4 * 2;
            *(uint2*)p = hi;
            *(uint2*)(p + W_PLANE) = lo;
        }
    }

    // ---- stage l2w transposed + l2b (used after barrier) ----
    for (int o = t; o < Cv * 64; o += THREADS) {
        const int c = o >> 6, j = o & 63;
        s_w[j][c] = __ldg(l2w + o);
    }
    if (t < Cv) s_b2[t] = __ldg(l2b + t);

    // ---- zero padded A rows 11..15 (both planes) ----
    if (t < 330) {
        const uint4 zz = make_uint4(0, 0, 0, 0);
        const int p = t / 165, i = t - p * 165;
        *(uint4*)(sm + A_OFF + p * A_PLANE + 11 * 528 + i * 16) = zz;
    }

    // ---- gather-mean + self into A planes: one row per warp, single round ----
    if (warp < S2N) {
        const int r = warp;
        const int m = (r == 0) ? 0 : __ldg(neigh + (b * Nv) * Kv + (r - 1));
        const int* nb = neigh + (b * Nv + m) * Kv;
        float4 a4 = make_float4(0.f, 0.f, 0.f, 0.f);
        #pragma unroll
        for (int k = 0; k < Kv; ++k) {
            const int idx = __ldg(nb + k);
            const float4 v = __ldg((const float4*)(x + (b * Nv + idx) * Fv) + lane);
            a4.x += v.x; a4.y += v.y; a4.z += v.z; a4.w += v.w;
        }
        const float inv = 1.0f / Kv;
        a4 = make_float4(a4.x * inv, a4.y * inv, a4.z * inv, a4.w * inv);
        uint2 hi, lo;
        split4(a4, hi, lo);
        char* p0 = sm + A_OFF + r * 528 + lane * 8;
        *(uint2*)p0 = hi;
        *(uint2*)(p0 + A_PLANE) = lo;
        const float4 hv = __ldg((const float4*)(x + (b * Nv + m) * Fv) + lane);
        split4(hv, hi, lo);
        *(uint2*)(p0 + 256) = hi;
        *(uint2*)(p0 + 256 + A_PLANE) = lo;
    }
    __syncthreads();

    // ---- MMA: warps 0-7 only; 16m x 128n, K=256; each warp owns 16 cols ----
    const int qr = lane >> 2, qc = (lane & 3) * 2;
    if (warp < 8) {
        const int wn = warp * 16;
        uint32_t aaddr[2], baddr[2];
        {
            const int ra = (lane & 7) + ((lane >> 3) & 1) * 8;
            const int ca = ((lane >> 4) & 1) * 16;
            #pragma unroll
            for (int p = 0; p < 2; ++p)
                aaddr[p] = smb + A_OFF + p * A_PLANE + ra * 528 + ca;
            const int rb = (lane & 7) + ((lane >> 4) & 1) * 8;
            const int cb = ((lane >> 3) & 1) * 16;
            #pragma unroll
            for (int p = 0; p < 2; ++p)
                baddr[p] = smb + p * W_PLANE + (wn + rb) * 528 + cb;
        }

        float acc[2][4];
        #pragma unroll
        for (int nf = 0; nf < 2; ++nf)
            #pragma unroll
            for (int q = 0; q < 4; ++q) acc[nf][q] = 0.f;

        #pragma unroll
        for (int ks = 0; ks < 16; ++ks) {
            const uint32_t off = ks * 32;
            uint32_t AH[4], AL[4], BH[4], BL[4];
            ldsm_x4(AH, aaddr[0] + off);
            ldsm_x4(AL, aaddr[1] + off);
            ldsm_x4(BH, baddr[0] + off);
            ldsm_x4(BL, baddr[1] + off);
            #pragma unroll
            for (int nf = 0; nf < 2; ++nf) {
                const uint32_t bh0 = BH[nf * 2], bh1 = BH[nf * 2 + 1];
                const uint32_t bl0 = BL[nf * 2], bl1 = BL[nf * 2 + 1];
                mma_bf16(acc[nf], AH, bh0, bh1);
                mma_bf16(acc[nf], AL, bh0, bh1);
                mma_bf16(acc[nf], AH, bl0, bl1);
            }
        }

        // epilogue: + bias, write h1 cone (rows 0..10) to smem
        float* h1s = (float*)(sm + H1_OFF);   // [11][128]
        #pragma unroll
        for (int nf = 0; nf < 2; ++nf) {
            const int col = wn + nf * 8 + qc;
            const float b0 = __ldg(b_sage + col);
            const float b1 = __ldg(b_sage + col + 1);
            h1s[qr * 128 + col]     = acc[nf][0] + b0;
            h1s[qr * 128 + col + 1] = acc[nf][1] + b1;
            if (qr < 3) {
                h1s[(qr + 8) * 128 + col]     = acc[nf][2] + b0;
                h1s[(qr + 8) * 128 + col + 1] = acc[nf][3] + b1;
            }
        }
    }
    __syncthreads();

    // ---- a2 = [mean_{s=1..10} h1s[s], h1s[0]] ----
    {
        float* h1s = (float*)(sm + H1_OFF);
        if (t < 128) {
            float a = 0.f;
            #pragma unroll
            for (int s = 1; s < 11; ++s) a += h1s[s * 128 + t];
            a2[t] = a * (1.0f / Kv);
            a2[128 + t] = h1s[t];
        }
    }
    __syncthreads();

    // ---- h2[j] = a2 . W1[j,:] + b1[j]  (fp32 exact, 4-way split, 2 accs) ----
    {
        const int j = t & 127, qtr = t >> 7;     // 4 quarters of 64 k each
        const float4* wr = (const float4*)(w_sage + 32768 + j * 256 + qtr * 64);
        const float4* ar = (const float4*)(a2 + qtr * 64);
        float s0 = 0.f, s1 = 0.f;
        #pragma unroll
        for (int q = 0; q < 16; q += 2) {
            const float4 w0 = __ldg(wr + q),     a0 = ar[q];
            const float4 w1 = __ldg(wr + q + 1), a1 = ar[q + 1];
            s0 = fmaf(a0.x, w0.x, s0); s0 = fmaf(a0.y, w0.y, s0);
            s0 = fmaf(a0.z, w0.z, s0); s0 = fmaf(a0.w, w0.w, s0);
            s1 = fmaf(a1.x, w1.x, s1); s1 = fmaf(a1.y, w1.y, s1);
            s1 = fmaf(a1.z, w1.z, s1); s1 = fmaf(a1.w, w1.w, s1);
        }
        redh[qtr][j] = s0 + s1;
    }
    __syncthreads();
    if (t < 128)
        h2s[t] = (redh[0][t] + redh[1][t]) + (redh[2][t] + redh[3][t])
               + __ldg(b_sage + 128 + t);
    __syncthreads();

    // ---- z[b,j] = h2 . l1w[j,:] + l1b[j]  (8-way split) ----
    {
        const int j = t & 63, seg = t >> 6;      // 8 segments of 16 k each
        const float4* wr = (const float4*)(l1w + j * 128 + seg * 16);
        const float4* hr = (const float4*)(h2s + seg * 16);
        float s0 = 0.f, s1 = 0.f;
        {
            const float4 w0 = __ldg(wr + 0), a0 = hr[0];
            const float4 w1 = __ldg(wr + 1), a1 = hr[1];
            const float4 w2 = __ldg(wr + 2), a2v = hr[2];
            const float4 w3 = __ldg(wr + 3), a3 = hr[3];
            s0 = fmaf(a0.x, w0.x, s0); s0 = fmaf(a0.y, w0.y, s0);
            s0 = fmaf(a0.z, w0.z, s0); s0 = fmaf(a0.w, w0.w, s0);
            s1 = fmaf(a1.x, w1.x, s1); s1 = fmaf(a1.y, w1.y, s1);
            s1 = fmaf(a1.z, w1.z, s1); s1 = fmaf(a1.w, w1.w, s1);
            s0 = fmaf(a2v.x, w2.x, s0); s0 = fmaf(a2v.y, w2.y, s0);
            s0 = fmaf(a2v.z, w2.z, s0); s0 = fmaf(a2v.w, w2.w, s0);
            s1 = fmaf(a3.x, w3.x, s1); s1 = fmaf(a3.y, w3.y, s1);
            s1 = fmaf(a3.z, w3.z, s1); s1 = fmaf(a3.w, w3.w, s1);
        }
        redl[seg][j] = s0 + s1;
    }
    __syncthreads();

    // ---- own z row -> smem + BN accumulators (RED: return value unused) ----
    if (t < 64) {
        float zv = __ldg(l1b + t);
        #pragma unroll
        for (int g = 0; g < 8; ++g) zv += redl[g][t];
        s_r[t] = zv;
        atomicAdd(&g_sum[bank][t], zv);          // -> REDG (no return)
        atomicAdd(&g_sumsq[bank][t], zv * zv);   // -> REDG (no return)
    }

    // ================= device-wide epoch barrier =================
    // grid=128 <= 148 SMs at 1 CTA/SM: all CTAs co-resident, spin is safe.
    // Arrive: return-less atomicAdd (REDG, ~0.854 cyc/lane single-addr).
    // Spin:   plain volatile load (no LTS atomic-ALU serialization).
    __threadfence();
    __syncthreads();
    if (t == 0) {
        atomicAdd(&g_bar1, 1u);                  // result unused -> RED
        const unsigned target = ep * (unsigned)Bv + (unsigned)Bv;
        while (*(volatile unsigned int*)&g_bar1 < target) { }
    }
    __syncthreads();

    // ================= phase B: finish own row only =================
    if (t < 64) {
        const float s  = __ldcg(&g_sum[bank][t]);   // .cg: bypass L1, read L2
        const float q  = __ldcg(&g_sumsq[bank][t]);
        const float mu  = s * (1.0f / Bv);
        const float var = q * (1.0f / Bv) - mu * mu;
        const float sc  = __ldg(gamma + t) * rsqrtf(var + 1e-5f);
        const float sh  = __ldg(beta + t) - mu * sc;
        s_r[t] = fmaxf(s_r[t] * sc + sh, 0.f);
    } else if (b == 0 && t >= 64 && t < 128) {
        // CTA 0 zeroes the other bank for the NEXT launch (overlapped, no tail)
        const int j = t - 64;
        g_sum[bank ^ 1][j]   = 0.f;
        g_sumsq[bank ^ 1][j] = 0.f;
    }
    __syncthreads();

    // warp 0: lin2 (2 cols per lane, even/odd-j dual accs) + softmax via shuffle
    if (warp == 0) {
        float lgA0 = s_b2[lane], lgA1 = 0.f;          // lane < 32 < Cv
        const bool hasB = (lane < Cv - 32);
        float lgB0 = hasB ? s_b2[lane + 32] : 0.f, lgB1 = 0.f;
        #pragma unroll 8
        for (int j = 0; j < 64; j += 2) {
            const float z0 = s_r[j], z1 = s_r[j + 1];
            lgA0 = fmaf(z0, s_w[j][lane], lgA0);
            lgA1 = fmaf(z1, s_w[j + 1][lane], lgA1);
            if (hasB) {
                lgB0 = fmaf(z0, s_w[j][lane + 32], lgB0);
                lgB1 = fmaf(z1, s_w[j + 1][lane + 32], lgB1);
            }
        }
        const float lgA = lgA0 + lgA1;
        const float lgB = lgB0 + lgB1;
        float m = lgA;
        if (hasB) m = fmaxf(m, lgB);
        #pragma unroll
        for (int o = 16; o > 0; o >>= 1)
            m = fmaxf(m, __shfl_xor_sync(0xFFFFFFFF, m, o));
        float eA = expf(lgA - m);
        float eB = hasB ? expf(lgB - m) : 0.f;
        float s = eA + eB;
        #pragma unroll
        for (int o = 16; o > 0; o >>= 1)
            s += __shfl_xor_sync(0xFFFFFFFF, s, o);
        const float r = 1.0f / s;
        out[b * Cv + lane] = eA * r;
        if (hasB) out[b * Cv + lane + 32] = eB * r;
    }

    // ---- advance epoch (single writer; launches serialize across replays) ----
    if (b == 0 && t == 0)
        *(volatile unsigned int*)&g_epoch = ep + 1u;
}

extern "C" void kernel_launch(void* const* d_in, const int* in_sizes, int n_in,
                              void* d_out, int out_size) {
    const float* x      = (const float*)d_in[0];
    const int*   neigh  = (const int*)  d_in[1];
    const float* w_sage = (const float*)d_in[2];
    const float* b_sage = (const float*)d_in[3];
    const float* l1w    = (const float*)d_in[4];
    const float* l1b    = (const float*)d_in[5];
    const float* gamma  = (const float*)d_in[6];
    const float* beta   = (const float*)d_in[7];
    const float* l2w    = (const float*)d_in[8];
    const float* l2b    = (const float*)d_in[9];
    float* out = (float*)d_out;

    cudaFuncSetAttribute(fused_all_kernel,
                         cudaFuncAttributeMaxDynamicSharedMemorySize, SMEM_BYTES);

    fused_all_kernel<<<Bv, THREADS, SMEM_BYTES>>>(x, neigh, w_sage, b_sage,
                                                  l1w, l1b, gamma, beta, l2w, l2b,
                                                  out);
}